// round 15
// baseline (speedup 1.0000x reference)
#include <cuda_runtime.h>
#include <cuda_bf16.h>
#include <math.h>
#include <cstdint>

// Problem constants
#define TAU   0.07f
#define BB    8
#define CC    128
#define HH    512
#define WW    512
#define HWSZ  (HH*WW)
#define KK    64
#define NNEG  7
#define PP    4096
#define NQ    (BB*KK)          // 512
#define SROW  144              // smem row stride in bytes (72 bf16)
#define TBUF  (128 * SROW)     // one tensor buffer (18432 B)
#define BUF   (4 * TBUF)       // one kc stage, 4 tensors (73728 B)
#define GSMEM (2 * BUF)        // double buffered (147456 B)

// Device scratch (allocation-free)
__device__ float4 g_q[NQ * 32];        // RAW gathered queries fp32 [NQ][C]
__device__ uint4  g_q_hi[NQ * 16];     // queries bf16 hi
__device__ uint4  g_q_lo[NQ * 16];     // queries bf16 lo residual
__device__ uint4  g_p_hi[PP * 16];     // NORMALIZED pool bf16 hi
__device__ uint4  g_p_lo[PP * 16];     // normalized pool bf16 lo residual
__device__ float  g_pmax_val[NQ * 32]; // per (query, pblk) max dot(q, p_norm)
__device__ float  g_qinv[NQ];          // query inverse norms
__device__ float  g_nl[NQ * NNEG];     // precomputed negative logits
__device__ float  g_loss_blk[64];
__device__ int    g_ticket;

#define MMA_BF16(D, A0, A1, A2, A3, B0, B1)                                   \
    asm volatile(                                                             \
        "mma.sync.aligned.m16n8k16.row.col.f32.bf16.bf16.f32 "                \
        "{%0,%1,%2,%3}, {%4,%5,%6,%7}, {%8,%9}, {%0,%1,%2,%3};"               \
        : "+f"(D[0]), "+f"(D[1]), "+f"(D[2]), "+f"(D[3])                      \
        : "r"(A0), "r"(A1), "r"(A2), "r"(A3), "r"(B0), "r"(B1))

#define LDSM_X4(R, ADDR)                                                      \
    asm volatile("ldmatrix.sync.aligned.m8n8.x4.shared.b16 {%0,%1,%2,%3}, [%4];" \
        : "=r"((R)[0]), "=r"((R)[1]), "=r"((R)[2]), "=r"((R)[3]) : "r"(ADDR))

#define CP16(dst, src)                                                        \
    asm volatile("cp.async.ca.shared.global [%0], [%1], 16;"                  \
        :: "r"(dst), "l"(src))

__device__ __forceinline__ uint32_t smem_u32(const void* p) {
    uint32_t a;
    asm("{ .reg .u64 t; cvta.to.shared.u64 t, %1; cvt.u32.u64 %0, t; }"
        : "=r"(a) : "l"(p));
    return a;
}

// ---------------------------------------------------------------------------
// Kernel 1: gather queries (TLB-friendly) + pool normalize/convert + reset.
// 256 blocks x 256 threads. (proven)
// ---------------------------------------------------------------------------
__global__ void __launch_bounds__(256)
prep_kernel(const float* __restrict__ qf,
            const float* __restrict__ pool,
            const int*   __restrict__ qidx) {
    int t = threadIdx.x, bid = blockIdx.x;
    int w = t >> 5, lane = t & 31;
    if (bid == 0 && t == 0) g_ticket = 0;

    int e = bid * 256 + t;
    int k = e & 63;
    int c = (e >> 6) & 127;
    int b = e >> 13;
    int idx = qidx[b * KK + k];
    float v = qf[(long)(b * CC + c) * HWSZ + idx];

    #pragma unroll
    for (int j = 0; j < 2; j++) {
        int r = bid * 16 + w * 2 + j;
        float4 u = ((const float4*)pool)[r * 32 + lane];
        float ss = u.x*u.x + u.y*u.y + u.z*u.z + u.w*u.w;
        #pragma unroll
        for (int o = 16; o > 0; o >>= 1) ss += __shfl_xor_sync(0xFFFFFFFFu, ss, o);
        float inv = 1.0f / fmaxf(sqrtf(ss), 1e-12f);
        float f[4] = {u.x * inv, u.y * inv, u.z * inv, u.w * inv};
        uint32_t h[2], l2[2];
        #pragma unroll
        for (int i = 0; i < 2; i++) {
            __nv_bfloat16 h0 = __float2bfloat16(f[2*i]);
            __nv_bfloat16 h1 = __float2bfloat16(f[2*i+1]);
            __nv_bfloat162 hp(h0, h1);
            __nv_bfloat162 lp(__float2bfloat16(f[2*i]   - __bfloat162float(h0)),
                              __float2bfloat16(f[2*i+1] - __bfloat162float(h1)));
            h[i]  = *(uint32_t*)&hp;
            l2[i] = *(uint32_t*)&lp;
        }
        ((uint2*)g_p_hi)[r * 32 + lane] = make_uint2(h[0], h[1]);
        ((uint2*)g_p_lo)[r * 32 + lane] = make_uint2(l2[0], l2[1]);
    }

    int qoff = (b * KK + k) * CC + c;
    ((float*)g_q)[qoff] = v;
    __nv_bfloat16 hv = __float2bfloat16(v);
    ((__nv_bfloat16*)g_q_hi)[qoff] = hv;
    ((__nv_bfloat16*)g_q_lo)[qoff] = __float2bfloat16(v - __bfloat162float(hv));
}

// ---------------------------------------------------------------------------
// Kernel 2: grid (33, 4), 256 threads.
// pblk < 32: tensor GEMM, tile 128q x 128p, cp.async double-buffered kc.
// pblk == 32: sideband negdot block — computes qinv + 7 negative logits for
//             its qblk's 128 queries (overlaps the GEMM wave; 132 <= 148 SMs).
// ---------------------------------------------------------------------------
__global__ void __launch_bounds__(256)
gemm_kernel(const float* __restrict__ negs) {
    extern __shared__ __align__(16) char sm[];
    int t = threadIdx.x, l = t & 31, w = t >> 5;
    int pblk = blockIdx.x, qblk = blockIdx.y;
    int qbase = qblk * 128;

    if (pblk == 32) {
        // ---- sideband: negatives + query inv norms for queries qbase..+127
        #pragma unroll
        for (int i = 0; i < 16; i++) {
            int q = qbase + w * 16 + i;
            int b = q >> 6, k = q & 63;
            float4 qv = g_q[q * 32 + l];
            float qss = qv.x*qv.x + qv.y*qv.y + qv.z*qv.z + qv.w*qv.w;
            float ss[NNEG], dt[NNEG];
            const float* nbase = negs + ((long)(b * KK + k)) * NNEG * CC;
            #pragma unroll
            for (int n = 0; n < NNEG; n++) {
                float4 nv = ((const float4*)(nbase + n * CC))[l];
                ss[n] = nv.x*nv.x + nv.y*nv.y + nv.z*nv.z + nv.w*nv.w;
                dt[n] = nv.x*qv.x + nv.y*qv.y + nv.z*qv.z + nv.w*qv.w;
            }
            #pragma unroll
            for (int o = 16; o > 0; o >>= 1) {
                qss += __shfl_xor_sync(0xFFFFFFFFu, qss, o);
                #pragma unroll
                for (int n = 0; n < NNEG; n++) {
                    ss[n] += __shfl_xor_sync(0xFFFFFFFFu, ss[n], o);
                    dt[n] += __shfl_xor_sync(0xFFFFFFFFu, dt[n], o);
                }
            }
            if (l == 0) {
                float invq = 1.0f / fmaxf(sqrtf(qss), 1e-12f);
                g_qinv[q] = invq;
                #pragma unroll
                for (int n = 0; n < NNEG; n++)
                    g_nl[q * NNEG + n] =
                        (dt[n] * invq / fmaxf(sqrtf(ss[n]), 1e-12f)) / TAU;
            }
        }
        return;
    }

    int pbase = pblk * 128;
    uint32_t sbase = smem_u32(sm);

    // ldmatrix lane-address bases (proven maps)
    uint32_t a_off = (uint32_t)((w * 16 + (l & 15)) * SROW + ((l >> 4) << 4));
    uint32_t b_row = (uint32_t)((l & 7) + ((l >> 4) << 3));
    uint32_t b_off0 = (b_row)      * SROW + (((l >> 3) & 1) << 4);
    uint32_t b_off1 = (b_row + 16) * SROW + (((l >> 3) & 1) << 4);

    // issue both kc stages via cp.async (double buffer)
    #pragma unroll
    for (int kc = 0; kc < 2; kc++) {
        uint32_t buf = sbase + kc * BUF;
        #pragma unroll
        for (int i = 0; i < 4; i++) {
            int idx = t + i * 256;           // 0..1023
            int r = idx >> 3, c8 = idx & 7;
            uint32_t dst = buf + r * SROW + c8 * 16;
            int gq = (qbase + r) * 16 + kc * 8 + c8;
            int gp = (pbase + r) * 16 + kc * 8 + c8;
            CP16(dst,            &g_q_hi[gq]);
            CP16(dst + TBUF,     &g_q_lo[gq]);
            CP16(dst + 2 * TBUF, &g_p_hi[gp]);
            CP16(dst + 3 * TBUF, &g_p_lo[gp]);
        }
        asm volatile("cp.async.commit_group;" ::: "memory");
    }

    float d[16][4];
    #pragma unroll
    for (int n = 0; n < 16; n++)
        #pragma unroll
        for (int i = 0; i < 4; i++) d[n][i] = 0.0f;

    #pragma unroll
    for (int kc = 0; kc < 2; kc++) {
        if (kc == 0)
            asm volatile("cp.async.wait_group 1;" ::: "memory");
        else
            asm volatile("cp.async.wait_group 0;" ::: "memory");
        __syncthreads();

        uint32_t qh_u = sbase + kc * BUF;
        uint32_t ql_u = qh_u + TBUF;
        uint32_t ph_u = qh_u + 2 * TBUF;
        uint32_t pl_u = qh_u + 3 * TBUF;

        #pragma unroll
        for (int kch = 0; kch < 4; kch++) {
            uint32_t ko = kch * 32;
            uint32_t ah[4], al[4];
            LDSM_X4(ah, qh_u + a_off + ko);
            LDSM_X4(al, ql_u + a_off + ko);
            #pragma unroll
            for (int pc = 0; pc < 4; pc++) {
                uint32_t po = pc * 32 * SROW;
                uint32_t bh[8], bl[8];
                LDSM_X4(bh,     ph_u + po + b_off0 + ko);
                LDSM_X4(bh + 4, ph_u + po + b_off1 + ko);
                LDSM_X4(bl,     pl_u + po + b_off0 + ko);
                LDSM_X4(bl + 4, pl_u + po + b_off1 + ko);
                #pragma unroll
                for (int n = 0; n < 4; n++) {
                    float* dd = d[pc * 4 + n];
                    uint32_t b0 = bh[n * 2], b1 = bh[n * 2 + 1];
                    uint32_t c0 = bl[n * 2], c1 = bl[n * 2 + 1];
                    MMA_BF16(dd, ah[0], ah[1], ah[2], ah[3], b0, b1);
                    MMA_BF16(dd, ah[0], ah[1], ah[2], ah[3], c0, c1);
                    MMA_BF16(dd, al[0], al[1], al[2], al[3], b0, b1);
                }
            }
        }
    }

    // epilogue: lane holds rows l/4 and l/4+8 of this warp's 16 q rows
    float m0 = -1e30f, m1 = -1e30f;
    #pragma unroll
    for (int n = 0; n < 16; n++) {
        m0 = fmaxf(m0, fmaxf(d[n][0], d[n][1]));
        m1 = fmaxf(m1, fmaxf(d[n][2], d[n][3]));
    }
    m0 = fmaxf(m0, __shfl_xor_sync(0xFFFFFFFFu, m0, 1));
    m0 = fmaxf(m0, __shfl_xor_sync(0xFFFFFFFFu, m0, 2));
    m1 = fmaxf(m1, __shfl_xor_sync(0xFFFFFFFFu, m1, 1));
    m1 = fmaxf(m1, __shfl_xor_sync(0xFFFFFFFFu, m1, 2));
    if ((l & 3) == 0) {
        int q0 = qbase + w * 16 + (l >> 2);
        g_pmax_val[q0 * 32 + pblk] = m0;
        g_pmax_val[(q0 + 8) * 32 + pblk] = m1;
    }
}

// ---------------------------------------------------------------------------
// Kernel 3: slim finalize — warp per query: max over 32 pmax partials,
// combine with precomputed neg logits; ticket-elected deterministic mean.
// grid = 64 blocks x 256 threads (8 warps = 8 queries per block).
// ---------------------------------------------------------------------------
__global__ void __launch_bounds__(256)
finalize_kernel(float* __restrict__ out) {
    __shared__ float loss_sm[8];
    __shared__ int   s_last;
    int t = threadIdx.x, w = t >> 5, lane = t & 31;
    int q = blockIdx.x * 8 + w;

    float v1 = g_pmax_val[q * 32 + lane];
    #pragma unroll
    for (int o = 16; o > 0; o >>= 1)
        v1 = fmaxf(v1, __shfl_xor_sync(0xFFFFFFFFu, v1, o));

    if (lane == 0) {
        float l0 = v1 * g_qinv[q] / TAU;
        float m = l0;
        float ln[NNEG];
        #pragma unroll
        for (int n = 0; n < NNEG; n++) {
            ln[n] = g_nl[q * NNEG + n];
            m = fmaxf(m, ln[n]);
        }
        float sum = expf(l0 - m);
        #pragma unroll
        for (int n = 0; n < NNEG; n++) sum += expf(ln[n] - m);
        loss_sm[w] = m + logf(sum) - l0;
    }
    __syncthreads();

    if (t == 0) {
        float s = 0.0f;
        #pragma unroll
        for (int i = 0; i < 8; i++) s += loss_sm[i];
        g_loss_blk[blockIdx.x] = s;
        __threadfence();
        int tk = atomicAdd(&g_ticket, 1);
        s_last = (tk == 63) ? 1 : 0;
    }
    __syncthreads();

    if (s_last && w == 0) {
        float s = g_loss_blk[lane] + g_loss_blk[lane + 32];
        #pragma unroll
        for (int o = 16; o > 0; o >>= 1) s += __shfl_xor_sync(0xFFFFFFFFu, s, o);
        if (lane == 0) out[0] = s / (float)NQ;
    }
}

extern "C" void kernel_launch(void* const* d_in, const int* in_sizes, int n_in,
                              void* d_out, int out_size) {
    const float* query_feat = (const float*)d_in[0];
    const float* pos_pool   = (const float*)d_in[1];
    const float* neg_protos = (const float*)d_in[2];
    const int*   query_idx  = (const int*)d_in[3];
    float* out = (float*)d_out;

    static int smem_set = 0;
    if (!smem_set) {
        cudaFuncSetAttribute(gemm_kernel,
                             cudaFuncAttributeMaxDynamicSharedMemorySize, GSMEM);
        smem_set = 1;
    }

    prep_kernel<<<256, 256>>>(query_feat, pos_pool, query_idx);
    dim3 grid(33, 4);
    gemm_kernel<<<grid, 256, GSMEM>>>(neg_protos);
    finalize_kernel<<<64, 256>>>(out);
}